// round 15
// baseline (speedup 1.0000x reference)
#include <cuda_runtime.h>

#define PB   128
#define PHW  256
#define HW   1024
#define BIMG 8
#define NPER 16
#define NB   128
#define NGRP 4
#define NBG  (NB / NGRP)          // 32 boxes per gather group

#define THREADS    384
#define DS_BLOCKS  128            // 128*384 = 49152 = PB*PB*3
#define GT_BLOCKS  (NGRP * PB)    // 512
#define PS_BLOCKS  (NB * 4)       // 512: 4 blocks per box, 32 rows each
#define ROWS_PER_CP 4
#define CP_BLOCKS  (BIMG * HW / ROWS_PER_CP)   // 2048
#define FN_BLOCKS  512            // 512*384 = 196608 = PHW*PHW*3
#define TOTAL_BLOCKS (DS_BLOCKS + GT_BLOCKS + PS_BLOCKS + CP_BLOCKS + FN_BLOCKS)

// Scratch (device globals — no allocation allowed)
__device__ float g_small[PB * PB * 3];              // downsampled patch
__device__ float g_smallT[PB * PB * 3];             // transposed copy (coalesced rot reads)
__device__ float g_nr[NGRP][PB][PB * 3];            // non-rot gather partials
__device__ float g_rt[NGRP][PB][PB * 3];            // rot gather partials (transposed)
__device__ int   g_sync[2];                          // [0]=ds done, [1]=gather done

// ---------------------------------------------------------------------------
// Role: antialiased bilinear downsample 256->128 (JAX triangle taps
// {0.25,0.75,0.75,0.25}, per-dim edge renormalization). Writes g_small + T.
// ---------------------------------------------------------------------------
__device__ void role_downsample(int bid, const float* __restrict__ patch) {
    int t = bid * THREADS + threadIdx.x;
    int c = t % 3;
    int j = (t / 3) % PB;
    int i = t / (3 * PB);

    const float w0[4] = {0.25f, 0.75f, 0.75f, 0.25f};
    int by = 2 * i - 1, bx = 2 * j - 1;
    float wy[4], wx[4], sy = 0.f, sx = 0.f;
#pragma unroll
    for (int u = 0; u < 4; u++) { int r = by + u; wy[u] = (r >= 0 && r < PHW) ? w0[u] : 0.f; sy += wy[u]; }
#pragma unroll
    for (int v = 0; v < 4; v++) { int q = bx + v; wx[v] = (q >= 0 && q < PHW) ? w0[v] : 0.f; sx += wx[v]; }

    float acc = 0.f;
#pragma unroll
    for (int u = 0; u < 4; u++) {
        if (wy[u] == 0.f) continue;
        int r = by + u;
        float rowacc = 0.f;
#pragma unroll
        for (int v = 0; v < 4; v++) {
            if (wx[v] == 0.f) continue;
            rowacc += wx[v] * __ldg(&patch[(r * PHW + (bx + v)) * 3 + c]);
        }
        acc += wy[u] * rowacc;
    }
    float val = acc / (sy * sx);
    g_small[t] = val;
    g_smallT[(j * PB + i) * 3 + c] = val;

    __syncthreads();
    __threadfence();
    if (threadIdx.x == 0) atomicAdd(&g_sync[0], 1);
}

// ---------------------------------------------------------------------------
// Role: gradient gather + inverse transform (coalesced for rot and non-rot).
// ---------------------------------------------------------------------------
__device__ void role_gather(int gb, const float* __restrict__ grads,
                            const int* __restrict__ box_yx,
                            const int* __restrict__ dec) {
    __shared__ int s_y[NBG], s_x[NBG], s_d[NBG], s_b[NBG];
    int tid = threadIdx.x;
    int g = gb >> 7;
    int r = gb & 127;

    if (tid < NBG) {
        int box = g * NBG + tid;
        s_y[tid] = __ldg(&box_yx[box * 2]);
        s_x[tid] = __ldg(&box_yx[box * 2 + 1]);
        s_d[tid] = (__ldg(&dec[box * 3]) > 0 ? 1 : 0) |
                   (__ldg(&dec[box * 3 + 1]) > 0 ? 2 : 0) |
                   (__ldg(&dec[box * 3 + 2]) > 0 ? 4 : 0);
        s_b[tid] = box >> 4;
    }
    __syncthreads();

    int j = tid / 3;
    int c = tid - 3 * j;

    float acc_nr = 0.f;
    float acc_rt = 0.f;
#pragma unroll 8
    for (int k = 0; k < NBG; ++k) {
        int d = s_d[k];
        size_t base = (size_t)s_b[k] * (HW * HW * 3);
        if (d & 1) {
            int row = s_y[k] + ((d & 4) ? r : (PB - 1 - r));
            int col = s_x[k] + ((d & 2) ? (PB - 1 - j) : j);
            acc_rt += __ldg(&grads[base + ((size_t)row * HW + col) * 3 + c]);
        } else {
            int row = s_y[k] + ((d & 4) ? (PB - 1 - r) : r);
            int col = s_x[k] + ((d & 2) ? (PB - 1 - j) : j);
            acc_nr += __ldg(&grads[base + ((size_t)row * HW + col) * 3 + c]);
        }
    }
    g_nr[g][r][tid] = acc_nr;
    g_rt[g][r][tid] = acc_rt;

    __syncthreads();
    __threadfence();
    if (tid == 0) atomicAdd(&g_sync[1], 1);
}

// ---------------------------------------------------------------------------
// Role: paste. 4 blocks per box, 32 rows each. Pure stores of the transformed
// tile; later-box-wins via a compacted overlap list (usually empty).
// ---------------------------------------------------------------------------
__device__ void role_paste(int pb_, const int* __restrict__ box_yx,
                           const int* __restrict__ dec,
                           float* __restrict__ out) {
    int box = pb_ >> 2;
    int rbase = (pb_ & 3) * 32;
    int b = box >> 4;
    int n = box & 15;
    int tid = threadIdx.x;

    __shared__ int s_y0, s_x0, s_d;
    __shared__ int l_y[NPER], l_x[NPER];
    __shared__ int l_cnt;

    if (tid == 0) {
        s_y0 = __ldg(&box_yx[box * 2]);
        s_x0 = __ldg(&box_yx[box * 2 + 1]);
        s_d = (__ldg(&dec[box * 3]) > 0 ? 1 : 0) |
              (__ldg(&dec[box * 3 + 1]) > 0 ? 2 : 0) |
              (__ldg(&dec[box * 3 + 2]) > 0 ? 4 : 0);
        l_cnt = 0;
    }
    __syncthreads();

    if (tid >= n + 1 && tid < NPER) {
        int mb = b * NPER + tid;
        int ym = __ldg(&box_yx[mb * 2]);
        int xm = __ldg(&box_yx[mb * 2 + 1]);
        int ylo = s_y0 + rbase, yhi = s_y0 + rbase + 32;
        bool ovl = (ym < yhi) && (ym + PB > ylo) &&
                   (xm < s_x0 + PB) && (xm + PB > s_x0);
        if (ovl) {
            int idx = atomicAdd(&l_cnt, 1);
            l_y[idx] = ym;
            l_x[idx] = xm;
        }
    }

    if (tid == 0) {
        volatile int* p = &g_sync[0];
        while (*p < DS_BLOCKS) __nanosleep(64);
    }
    __syncthreads();

    int rx = tid / 3;
    int c = tid - 3 * rx;
    int d = s_d;
    int x1 = (d & 2) ? (PB - 1 - rx) : rx;
    int xg = s_x0 + rx;
    int cnt = l_cnt;

    for (int r = 0; r < 32; r++) {
        int ry = rbase + r;
        int yg = s_y0 + ry;
        bool skip = false;
        for (int m = 0; m < cnt; m++) {
            if ((unsigned)(yg - l_y[m]) < (unsigned)PB &&
                (unsigned)(xg - l_x[m]) < (unsigned)PB) { skip = true; break; }
        }
        if (skip) continue;
        int y2 = (d & 4) ? (PB - 1 - ry) : ry;
        float val;
        if (d & 1) {
            int sx_ = PB - 1 - y2;
            val = g_smallT[(sx_ * PB + x1) * 3 + c];
        } else {
            val = g_small[(y2 * PB + x1) * 3 + c];
        }
        out[((size_t)(b * HW + yg) * HW + xg) * 3 + c] = val;
    }
}

// ---------------------------------------------------------------------------
// Role: streaming copy, 4 rows/block. 8-deep software pipeline:
// Phase A: pack 2-bit coverage codes for all 8 quads (bitmap tests, cheap).
// Phase B: issue all 8 predicated loads back-to-back (MLP=8).
// Phase C: 8 stores (coverage-masked; fully-covered quads skipped entirely).
// ---------------------------------------------------------------------------
__device__ void role_copy(int cb, const float* __restrict__ images,
                          const int* __restrict__ box_yx,
                          float* __restrict__ out) {
    int b = cb >> 8;                     // 256 blocks per image
    int ybase = (cb & 255) * ROWS_PER_CP;
    int tid = threadIdx.x;

    __shared__ unsigned s_cov[ROWS_PER_CP][32];   // 4 rows x 1024 bits

    for (int w = tid; w < ROWS_PER_CP * 32; w += THREADS)
        ((unsigned*)s_cov)[w] = 0u;
    __syncthreads();

    // build coverage: 64 threads = (box, row)
    if (tid < NPER * ROWS_PER_CP) {
        int bx_ = tid >> 2;              // box 0..15
        int r = tid & 3;                 // row 0..3
        int boxid = b * NPER + bx_;
        int y0 = __ldg(&box_yx[boxid * 2]);
        if ((unsigned)(ybase + r - y0) < (unsigned)PB) {
            int x0 = __ldg(&box_yx[boxid * 2 + 1]);
            int w0 = x0 >> 5, off = x0 & 31;
            if (off == 0) {
#pragma unroll
                for (int w = 0; w < 4; w++) atomicOr(&s_cov[r][w0 + w], 0xFFFFFFFFu);
            } else {
                atomicOr(&s_cov[r][w0], 0xFFFFFFFFu << off);
#pragma unroll
                for (int w = 1; w < 4; w++) atomicOr(&s_cov[r][w0 + w], 0xFFFFFFFFu);
                atomicOr(&s_cov[r][w0 + 4], 0xFFFFFFFFu >> (32 - off));
            }
        }
    }
    __syncthreads();

    size_t base4 = ((size_t)(b * HW + ybase)) * (HW * 3 / 4);
    const float4* src4 = (const float4*)images + base4;
    float4* dst4 = (float4*)out + base4;

    // quad index qq has only two values across all 8 quads; hoist pixel math
    int qq0 = tid;
    int qq1 = THREADS + tid;
    int pa0 = (qq0 * 4) / 3;
    int pa1 = (qq1 * 4) / 3;

    // Phase A: pack coverage codes (2 bits per quad)
    unsigned ccp = 0;
#pragma unroll
    for (int k = 0; k < 8; k++) {
        int row = k >> 1;
        int pa = (k & 1) ? pa1 : pa0;
        unsigned ca = (s_cov[row][pa >> 5] >> (pa & 31)) & 1u;
        unsigned cbit = (s_cov[row][(pa + 1) >> 5] >> ((pa + 1) & 31)) & 1u;
        ccp |= (ca | (cbit << 1)) << (2 * k);
    }

    // Phase B: all loads in flight together
    float4 v[8];
#pragma unroll
    for (int k = 0; k < 8; k++) {
        if (((ccp >> (2 * k)) & 3u) != 3u)
            v[k] = __ldcs(&src4[(k >> 1) * 768 + (k & 1) * THREADS + tid]);
    }

    // Phase C: stores
#pragma unroll
    for (int k = 0; k < 8; k++) {
        unsigned cc = (ccp >> (2 * k)) & 3u;
        if (cc == 3u) continue;          // fully pasted: paste blocks own it
        int qq = (k & 1) * THREADS + tid;
        float4* dp = &dst4[(k >> 1) * 768 + qq];
        if (cc == 0u) {
            __stcs(dp, v[k]);
        } else {
            int fo = qq * 4;
            int pa = fo / 3;
            float* df = (float*)dp;
            const float* vf = (const float*)&v[k];
#pragma unroll
            for (int e = 0; e < 4; e++) {
                int px = (fo + e) / 3;
                unsigned covered = (px == pa) ? (cc & 1u) : ((cc >> 1) & 1u);
                if (!covered) df[e] = vf[e];
            }
        }
    }
}

// ---------------------------------------------------------------------------
// Role: reduce gather partials + bilinear upsample 128->256 + analytic TV grad.
// ---------------------------------------------------------------------------
__device__ __forceinline__ float acc_at(int y, int x, int c) {
    float s = 0.f;
#pragma unroll
    for (int g = 0; g < NGRP; g++) {
        s += g_nr[g][y][x * 3 + c];
        s += g_rt[g][x][y * 3 + c];
    }
    return s;
}

__device__ void role_final(int fb, const float* __restrict__ patch,
                           float* __restrict__ agg) {
    if (threadIdx.x == 0) {
        volatile int* p = &g_sync[1];
        while (*p < GT_BLOCKS) __nanosleep(64);
    }
    __syncthreads();

    int t = fb * THREADS + threadIdx.x;
    int c = t % 3;
    int j = (t / 3) % PHW;
    int i = t / (PHW * 3);

    int ky = i >> 1, y0, y1; float wy0, wy1;
    if (i & 1) { y0 = ky;             y1 = min(ky + 1, PB - 1); wy0 = 0.75f; wy1 = 0.25f; }
    else       { y0 = max(ky - 1, 0); y1 = ky;                  wy0 = 0.25f; wy1 = 0.75f; }
    int kx = j >> 1, x0, x1; float wx0, wx1;
    if (j & 1) { x0 = kx;             x1 = min(kx + 1, PB - 1); wx0 = 0.75f; wx1 = 0.25f; }
    else       { x0 = max(kx - 1, 0); x1 = kx;                  wx0 = 0.25f; wx1 = 0.75f; }

    float v = wy0 * (wx0 * acc_at(y0, x0, c) + wx1 * acc_at(y0, x1, c))
            + wy1 * (wx0 * acc_at(y1, x0, c) + wx1 * acc_at(y1, x1, c));

    float pij = __ldg(&patch[(i * PHW + j) * 3 + c]);
    float a = (j < PHW - 1) ? (pij - __ldg(&patch[(i * PHW + j + 1) * 3 + c])) : 0.f;
    float bb = (i < PHW - 1) ? (pij - __ldg(&patch[((i + 1) * PHW + j) * 3 + c])) : 0.f;
    float g = (a + bb) * rsqrtf(a * a + bb * bb + 1e-12f);
    if (j > 0) {
        float pl = __ldg(&patch[(i * PHW + j - 1) * 3 + c]);
        float al = pl - pij;
        float bl = (i < PHW - 1) ? (pl - __ldg(&patch[((i + 1) * PHW + j - 1) * 3 + c])) : 0.f;
        g -= al * rsqrtf(al * al + bl * bl + 1e-12f);
    }
    if (i > 0) {
        float pu = __ldg(&patch[((i - 1) * PHW + j) * 3 + c]);
        float bu = pu - pij;
        float au = (j < PHW - 1) ? (pu - __ldg(&patch[((i - 1) * PHW + j + 1) * 3 + c])) : 0.f;
        g -= bu * rsqrtf(au * au + bu * bu + 1e-12f);
    }
    agg[t] = v + 0.5f * g;
}

// ---------------------------------------------------------------------------
// Mega kernel, R8 layout (best measured): ds | gather | paste | copy | final.
// ---------------------------------------------------------------------------
__global__ void __launch_bounds__(THREADS, 4) k_mega(
        const float* __restrict__ images, const float* __restrict__ grads,
        const float* __restrict__ patch,
        const int* __restrict__ box_yx, const int* __restrict__ dec,
        float* __restrict__ out, float* __restrict__ agg) {
    int bid = blockIdx.x;
    if (bid < DS_BLOCKS) {
        role_downsample(bid, patch);
    } else if (bid < DS_BLOCKS + GT_BLOCKS) {
        role_gather(bid - DS_BLOCKS, grads, box_yx, dec);
    } else if (bid < DS_BLOCKS + GT_BLOCKS + PS_BLOCKS) {
        role_paste(bid - (DS_BLOCKS + GT_BLOCKS), box_yx, dec, out);
    } else if (bid < DS_BLOCKS + GT_BLOCKS + PS_BLOCKS + CP_BLOCKS) {
        role_copy(bid - (DS_BLOCKS + GT_BLOCKS + PS_BLOCKS), images, box_yx, out);
    } else {
        role_final(bid - (DS_BLOCKS + GT_BLOCKS + PS_BLOCKS + CP_BLOCKS), patch, agg);
    }
}

// ---------------------------------------------------------------------------
extern "C" void kernel_launch(void* const* d_in, const int* in_sizes, int n_in,
                              void* d_out, int out_size) {
    const float* images = (const float*)d_in[0];
    const float* grads  = (const float*)d_in[1];
    const float* patch  = (const float*)d_in[2];
    const int*   box_yx = (const int*)d_in[3];
    const int*   dec    = (const int*)d_in[4];

    float* out = (float*)d_out;
    size_t img_elems = (size_t)BIMG * HW * HW * 3;
    float* agg = out + img_elems;

    void* sptr = nullptr;
    cudaGetSymbolAddress(&sptr, g_sync);
    cudaMemsetAsync(sptr, 0, 2 * sizeof(int));

    k_mega<<<TOTAL_BLOCKS, THREADS>>>(images, grads, patch, box_yx, dec, out, agg);
}

// round 16
// speedup vs baseline: 1.3439x; 1.3439x over previous
#include <cuda_runtime.h>

#define PB   128
#define PHW  256
#define HW   1024
#define BIMG 8
#define NPER 16
#define NB   128
#define NGRP 2
#define NBG  (NB / NGRP)          // 64 boxes per gather group

#define THREADS    384
#define DS_BLOCKS  128            // 128*384 = 49152 = PB*PB*3
#define GT_BLOCKS  (NGRP * PB)    // 256
#define PS_BLOCKS  (NB * 4)       // 512: 4 blocks per box, 32 rows each
#define ROWS_PER_CP 4
#define CP_BLOCKS  (BIMG * HW / ROWS_PER_CP)   // 2048
#define FN_BLOCKS  512            // 512*384 = 196608 = PHW*PHW*3
#define TOTAL_BLOCKS (DS_BLOCKS + GT_BLOCKS + PS_BLOCKS + CP_BLOCKS + FN_BLOCKS)

// Scratch (device globals — no allocation allowed)
__device__ float g_small[PB * PB * 3];              // downsampled patch
__device__ float g_smallT[PB * PB * 3];             // transposed copy (coalesced rot reads)
__device__ float g_nr[NGRP][PB][PB * 3];            // non-rot gather partials
__device__ float g_rt[NGRP][PB][PB * 3];            // rot gather partials (transposed)
__device__ int   g_sync[2];                          // [0]=ds done, [1]=gather done

// ---------------------------------------------------------------------------
// Role: antialiased bilinear downsample 256->128 (JAX triangle taps
// {0.25,0.75,0.75,0.25}, per-dim edge renormalization). Writes g_small + T.
// ---------------------------------------------------------------------------
__device__ void role_downsample(int bid, const float* __restrict__ patch) {
    int t = bid * THREADS + threadIdx.x;
    int c = t % 3;
    int j = (t / 3) % PB;
    int i = t / (3 * PB);

    const float w0[4] = {0.25f, 0.75f, 0.75f, 0.25f};
    int by = 2 * i - 1, bx = 2 * j - 1;
    float wy[4], wx[4], sy = 0.f, sx = 0.f;
#pragma unroll
    for (int u = 0; u < 4; u++) { int r = by + u; wy[u] = (r >= 0 && r < PHW) ? w0[u] : 0.f; sy += wy[u]; }
#pragma unroll
    for (int v = 0; v < 4; v++) { int q = bx + v; wx[v] = (q >= 0 && q < PHW) ? w0[v] : 0.f; sx += wx[v]; }

    float acc = 0.f;
#pragma unroll
    for (int u = 0; u < 4; u++) {
        if (wy[u] == 0.f) continue;
        int r = by + u;
        float rowacc = 0.f;
#pragma unroll
        for (int v = 0; v < 4; v++) {
            if (wx[v] == 0.f) continue;
            rowacc += wx[v] * __ldg(&patch[(r * PHW + (bx + v)) * 3 + c]);
        }
        acc += wy[u] * rowacc;
    }
    float val = acc / (sy * sx);
    g_small[t] = val;
    g_smallT[(j * PB + i) * 3 + c] = val;

    __syncthreads();
    __threadfence();
    if (threadIdx.x == 0) atomicAdd(&g_sync[0], 1);
}

// ---------------------------------------------------------------------------
// Role: gradient gather + inverse transform (coalesced for rot and non-rot).
// NGRP=2: 256 blocks x 64 boxes. Aggregate work unchanged; halves the partial
// arrays the final role must reduce.
// ---------------------------------------------------------------------------
__device__ void role_gather(int gb, const float* __restrict__ grads,
                            const int* __restrict__ box_yx,
                            const int* __restrict__ dec) {
    __shared__ int s_y[NBG], s_x[NBG], s_d[NBG], s_b[NBG];
    int tid = threadIdx.x;
    int g = gb >> 7;
    int r = gb & 127;

    if (tid < NBG) {
        int box = g * NBG + tid;
        s_y[tid] = __ldg(&box_yx[box * 2]);
        s_x[tid] = __ldg(&box_yx[box * 2 + 1]);
        s_d[tid] = (__ldg(&dec[box * 3]) > 0 ? 1 : 0) |
                   (__ldg(&dec[box * 3 + 1]) > 0 ? 2 : 0) |
                   (__ldg(&dec[box * 3 + 2]) > 0 ? 4 : 0);
        s_b[tid] = box >> 4;
    }
    __syncthreads();

    int j = tid / 3;
    int c = tid - 3 * j;

    float acc_nr = 0.f;
    float acc_rt = 0.f;
#pragma unroll 8
    for (int k = 0; k < NBG; ++k) {
        int d = s_d[k];
        size_t base = (size_t)s_b[k] * (HW * HW * 3);
        if (d & 1) {
            int row = s_y[k] + ((d & 4) ? r : (PB - 1 - r));
            int col = s_x[k] + ((d & 2) ? (PB - 1 - j) : j);
            acc_rt += __ldg(&grads[base + ((size_t)row * HW + col) * 3 + c]);
        } else {
            int row = s_y[k] + ((d & 4) ? (PB - 1 - r) : r);
            int col = s_x[k] + ((d & 2) ? (PB - 1 - j) : j);
            acc_nr += __ldg(&grads[base + ((size_t)row * HW + col) * 3 + c]);
        }
    }
    g_nr[g][r][tid] = acc_nr;
    g_rt[g][r][tid] = acc_rt;

    __syncthreads();
    __threadfence();
    if (tid == 0) atomicAdd(&g_sync[1], 1);
}

// ---------------------------------------------------------------------------
// Role: paste. 4 blocks per box, 32 rows each. Pure stores of the transformed
// tile; later-box-wins via a compacted overlap list (usually empty).
// ---------------------------------------------------------------------------
__device__ void role_paste(int pb_, const int* __restrict__ box_yx,
                           const int* __restrict__ dec,
                           float* __restrict__ out) {
    int box = pb_ >> 2;
    int rbase = (pb_ & 3) * 32;
    int b = box >> 4;
    int n = box & 15;
    int tid = threadIdx.x;

    __shared__ int s_y0, s_x0, s_d;
    __shared__ int l_y[NPER], l_x[NPER];
    __shared__ int l_cnt;

    if (tid == 0) {
        s_y0 = __ldg(&box_yx[box * 2]);
        s_x0 = __ldg(&box_yx[box * 2 + 1]);
        s_d = (__ldg(&dec[box * 3]) > 0 ? 1 : 0) |
              (__ldg(&dec[box * 3 + 1]) > 0 ? 2 : 0) |
              (__ldg(&dec[box * 3 + 2]) > 0 ? 4 : 0);
        l_cnt = 0;
    }
    __syncthreads();

    if (tid >= n + 1 && tid < NPER) {
        int mb = b * NPER + tid;
        int ym = __ldg(&box_yx[mb * 2]);
        int xm = __ldg(&box_yx[mb * 2 + 1]);
        int ylo = s_y0 + rbase, yhi = s_y0 + rbase + 32;
        bool ovl = (ym < yhi) && (ym + PB > ylo) &&
                   (xm < s_x0 + PB) && (xm + PB > s_x0);
        if (ovl) {
            int idx = atomicAdd(&l_cnt, 1);
            l_y[idx] = ym;
            l_x[idx] = xm;
        }
    }

    if (tid == 0) {
        volatile int* p = &g_sync[0];
        while (*p < DS_BLOCKS) __nanosleep(64);
    }
    __syncthreads();

    int rx = tid / 3;
    int c = tid - 3 * rx;
    int d = s_d;
    int x1 = (d & 2) ? (PB - 1 - rx) : rx;
    int xg = s_x0 + rx;
    int cnt = l_cnt;

    for (int r = 0; r < 32; r++) {
        int ry = rbase + r;
        int yg = s_y0 + ry;
        bool skip = false;
        for (int m = 0; m < cnt; m++) {
            if ((unsigned)(yg - l_y[m]) < (unsigned)PB &&
                (unsigned)(xg - l_x[m]) < (unsigned)PB) { skip = true; break; }
        }
        if (skip) continue;
        int y2 = (d & 4) ? (PB - 1 - ry) : ry;
        float val;
        if (d & 1) {
            int sx_ = PB - 1 - y2;
            val = g_smallT[(sx_ * PB + x1) * 3 + c];
        } else {
            val = g_small[(y2 * PB + x1) * 3 + c];
        }
        out[((size_t)(b * HW + yg) * HW + xg) * 3 + c] = val;
    }
}

// ---------------------------------------------------------------------------
// Role: streaming copy, 4 rows/block, coverage-masked stores. Never waits.
// Fully-covered quads skip both the read and the write (paste blocks own them).
// ---------------------------------------------------------------------------
__device__ void role_copy(int cb, const float* __restrict__ images,
                          const int* __restrict__ box_yx,
                          float* __restrict__ out) {
    int b = cb >> 8;                     // 256 blocks per image
    int ybase = (cb & 255) * ROWS_PER_CP;
    int tid = threadIdx.x;

    __shared__ unsigned s_cov[ROWS_PER_CP][32];   // 4 rows x 1024 bits

    if (tid < ROWS_PER_CP * 32) ((unsigned*)s_cov)[tid] = 0u;   // 128 < 384: safe
    __syncthreads();

    // build coverage: 64 threads = (box, row)
    if (tid < NPER * ROWS_PER_CP) {
        int bx_ = tid >> 2;              // box 0..15
        int r = tid & 3;                 // row 0..3
        int boxid = b * NPER + bx_;
        int y0 = __ldg(&box_yx[boxid * 2]);
        if ((unsigned)(ybase + r - y0) < (unsigned)PB) {
            int x0 = __ldg(&box_yx[boxid * 2 + 1]);
            int w0 = x0 >> 5, off = x0 & 31;
            if (off == 0) {
#pragma unroll
                for (int w = 0; w < 4; w++) atomicOr(&s_cov[r][w0 + w], 0xFFFFFFFFu);
            } else {
                atomicOr(&s_cov[r][w0], 0xFFFFFFFFu << off);
#pragma unroll
                for (int w = 1; w < 4; w++) atomicOr(&s_cov[r][w0 + w], 0xFFFFFFFFu);
                atomicOr(&s_cov[r][w0 + 4], 0xFFFFFFFFu >> (32 - off));
            }
        }
    }
    __syncthreads();

    size_t base4 = ((size_t)(b * HW + ybase)) * (HW * 3 / 4);
    const float4* src4 = (const float4*)images + base4;
    float4* dst4 = (float4*)out + base4;

#pragma unroll
    for (int h = 0; h < 2; h++) {
        float4 v[4];
        int cc[4];
#pragma unroll
        for (int k = 0; k < 4; k++) {
            int q = h * 4 + k;
            int row = q >> 1;
            int qq = (q & 1) * THREADS + tid;         // float4 idx in row
            int pa = (qq * 4) / 3;                    // first pixel spanned
            int ca = (s_cov[row][pa >> 5] >> (pa & 31)) & 1;
            int cbit = (s_cov[row][(pa + 1) >> 5] >> ((pa + 1) & 31)) & 1;
            cc[k] = ca | (cbit << 1);
            if (cc[k] != 3)
                v[k] = __ldcs(&src4[row * 768 + qq]);
        }
#pragma unroll
        for (int k = 0; k < 4; k++) {
            if (cc[k] == 3) continue;                 // fully pasted
            int q = h * 4 + k;
            int row = q >> 1;
            int qq = (q & 1) * THREADS + tid;
            float4* dp = &dst4[row * 768 + qq];
            if (cc[k] == 0) {
                __stcs(dp, v[k]);
            } else {
                int fo = qq * 4;
                int pa = fo / 3;
                float* df = (float*)dp;
                const float* vf = (const float*)&v[k];
#pragma unroll
                for (int e = 0; e < 4; e++) {
                    int px = (fo + e) / 3;
                    int covered = (px == pa) ? (cc[k] & 1) : ((cc[k] >> 1) & 1);
                    if (!covered) df[e] = vf[e];
                }
            }
        }
    }
}

// ---------------------------------------------------------------------------
// Role: reduce gather partials + bilinear upsample 128->256 + analytic TV grad.
// NGRP=2: 16 L2 loads per output element (was 32).
// ---------------------------------------------------------------------------
__device__ __forceinline__ float acc_at(int y, int x, int c) {
    float s = 0.f;
#pragma unroll
    for (int g = 0; g < NGRP; g++) {
        s += g_nr[g][y][x * 3 + c];
        s += g_rt[g][x][y * 3 + c];
    }
    return s;
}

__device__ void role_final(int fb, const float* __restrict__ patch,
                           float* __restrict__ agg) {
    if (threadIdx.x == 0) {
        volatile int* p = &g_sync[1];
        while (*p < GT_BLOCKS) __nanosleep(64);
    }
    __syncthreads();

    int t = fb * THREADS + threadIdx.x;
    int c = t % 3;
    int j = (t / 3) % PHW;
    int i = t / (PHW * 3);

    int ky = i >> 1, y0, y1; float wy0, wy1;
    if (i & 1) { y0 = ky;             y1 = min(ky + 1, PB - 1); wy0 = 0.75f; wy1 = 0.25f; }
    else       { y0 = max(ky - 1, 0); y1 = ky;                  wy0 = 0.25f; wy1 = 0.75f; }
    int kx = j >> 1, x0, x1; float wx0, wx1;
    if (j & 1) { x0 = kx;             x1 = min(kx + 1, PB - 1); wx0 = 0.75f; wx1 = 0.25f; }
    else       { x0 = max(kx - 1, 0); x1 = kx;                  wx0 = 0.25f; wx1 = 0.75f; }

    float v = wy0 * (wx0 * acc_at(y0, x0, c) + wx1 * acc_at(y0, x1, c))
            + wy1 * (wx0 * acc_at(y1, x0, c) + wx1 * acc_at(y1, x1, c));

    float pij = __ldg(&patch[(i * PHW + j) * 3 + c]);
    float a = (j < PHW - 1) ? (pij - __ldg(&patch[(i * PHW + j + 1) * 3 + c])) : 0.f;
    float bb = (i < PHW - 1) ? (pij - __ldg(&patch[((i + 1) * PHW + j) * 3 + c])) : 0.f;
    float g = (a + bb) * rsqrtf(a * a + bb * bb + 1e-12f);
    if (j > 0) {
        float pl = __ldg(&patch[(i * PHW + j - 1) * 3 + c]);
        float al = pl - pij;
        float bl = (i < PHW - 1) ? (pl - __ldg(&patch[((i + 1) * PHW + j - 1) * 3 + c])) : 0.f;
        g -= al * rsqrtf(al * al + bl * bl + 1e-12f);
    }
    if (i > 0) {
        float pu = __ldg(&patch[((i - 1) * PHW + j) * 3 + c]);
        float bu = pu - pij;
        float au = (j < PHW - 1) ? (pu - __ldg(&patch[((i - 1) * PHW + j + 1) * 3 + c])) : 0.f;
        g -= bu * rsqrtf(au * au + bu * bu + 1e-12f);
    }
    agg[t] = v + 0.5f * g;
}

// ---------------------------------------------------------------------------
// Mega kernel, R8 layout (best measured): ds | gather | paste | copy | final.
// ---------------------------------------------------------------------------
__global__ void __launch_bounds__(THREADS, 4) k_mega(
        const float* __restrict__ images, const float* __restrict__ grads,
        const float* __restrict__ patch,
        const int* __restrict__ box_yx, const int* __restrict__ dec,
        float* __restrict__ out, float* __restrict__ agg) {
    int bid = blockIdx.x;
    if (bid < DS_BLOCKS) {
        role_downsample(bid, patch);
    } else if (bid < DS_BLOCKS + GT_BLOCKS) {
        role_gather(bid - DS_BLOCKS, grads, box_yx, dec);
    } else if (bid < DS_BLOCKS + GT_BLOCKS + PS_BLOCKS) {
        role_paste(bid - (DS_BLOCKS + GT_BLOCKS), box_yx, dec, out);
    } else if (bid < DS_BLOCKS + GT_BLOCKS + PS_BLOCKS + CP_BLOCKS) {
        role_copy(bid - (DS_BLOCKS + GT_BLOCKS + PS_BLOCKS), images, box_yx, out);
    } else {
        role_final(bid - (DS_BLOCKS + GT_BLOCKS + PS_BLOCKS + CP_BLOCKS), patch, agg);
    }
}

// ---------------------------------------------------------------------------
extern "C" void kernel_launch(void* const* d_in, const int* in_sizes, int n_in,
                              void* d_out, int out_size) {
    const float* images = (const float*)d_in[0];
    const float* grads  = (const float*)d_in[1];
    const float* patch  = (const float*)d_in[2];
    const int*   box_yx = (const int*)d_in[3];
    const int*   dec    = (const int*)d_in[4];

    float* out = (float*)d_out;
    size_t img_elems = (size_t)BIMG * HW * HW * 3;
    float* agg = out + img_elems;

    void* sptr = nullptr;
    cudaGetSymbolAddress(&sptr, g_sync);
    cudaMemsetAsync(sptr, 0, 2 * sizeof(int));

    k_mega<<<TOTAL_BLOCKS, THREADS>>>(images, grads, patch, box_yx, dec, out, agg);
}

// round 17
// speedup vs baseline: 1.3448x; 1.0007x over previous
#include <cuda_runtime.h>

#define PB   128
#define PHW  256
#define HW   1024
#define BIMG 8
#define NPER 16
#define NB   128
#define NGRP 2
#define NBG  (NB / NGRP)          // 64 boxes per gather group

#define THREADS    384
#define DS_BLOCKS  128            // 128*384 = 49152 = PB*PB*3
#define GT_BLOCKS  (NGRP * PB)    // 256
#define PS_BLOCKS  (NB * 4)       // 512: 4 blocks per box, 32 rows each
#define ROWS_PER_CP 8
#define CP_BLOCKS  (BIMG * HW / ROWS_PER_CP)   // 1024
#define FN_BLOCKS  512            // 512*384 = 196608 = PHW*PHW*3
#define TOTAL_BLOCKS (DS_BLOCKS + GT_BLOCKS + PS_BLOCKS + CP_BLOCKS + FN_BLOCKS)

// Scratch (device globals — no allocation allowed)
__device__ float g_small[PB * PB * 3];              // downsampled patch
__device__ float g_smallT[PB * PB * 3];             // transposed copy (coalesced rot reads)
__device__ float g_nr[NGRP][PB][PB * 3];            // non-rot gather partials
__device__ float g_rt[NGRP][PB][PB * 3];            // rot gather partials (transposed)
__device__ int   g_sync[2];                          // [0]=ds done, [1]=gather done

// ---------------------------------------------------------------------------
// Role: antialiased bilinear downsample 256->128 (JAX triangle taps
// {0.25,0.75,0.75,0.25}, per-dim edge renormalization). Writes g_small + T.
// ---------------------------------------------------------------------------
__device__ void role_downsample(int bid, const float* __restrict__ patch) {
    int t = bid * THREADS + threadIdx.x;
    int c = t % 3;
    int j = (t / 3) % PB;
    int i = t / (3 * PB);

    const float w0[4] = {0.25f, 0.75f, 0.75f, 0.25f};
    int by = 2 * i - 1, bx = 2 * j - 1;
    float wy[4], wx[4], sy = 0.f, sx = 0.f;
#pragma unroll
    for (int u = 0; u < 4; u++) { int r = by + u; wy[u] = (r >= 0 && r < PHW) ? w0[u] : 0.f; sy += wy[u]; }
#pragma unroll
    for (int v = 0; v < 4; v++) { int q = bx + v; wx[v] = (q >= 0 && q < PHW) ? w0[v] : 0.f; sx += wx[v]; }

    float acc = 0.f;
#pragma unroll
    for (int u = 0; u < 4; u++) {
        if (wy[u] == 0.f) continue;
        int r = by + u;
        float rowacc = 0.f;
#pragma unroll
        for (int v = 0; v < 4; v++) {
            if (wx[v] == 0.f) continue;
            rowacc += wx[v] * __ldg(&patch[(r * PHW + (bx + v)) * 3 + c]);
        }
        acc += wy[u] * rowacc;
    }
    float val = acc / (sy * sx);
    g_small[t] = val;
    g_smallT[(j * PB + i) * 3 + c] = val;

    __syncthreads();
    __threadfence();
    if (threadIdx.x == 0) atomicAdd(&g_sync[0], 1);
}

// ---------------------------------------------------------------------------
// Role: gradient gather + inverse transform (coalesced for rot and non-rot).
// NGRP=2: 256 blocks x 64 boxes.
// ---------------------------------------------------------------------------
__device__ void role_gather(int gb, const float* __restrict__ grads,
                            const int* __restrict__ box_yx,
                            const int* __restrict__ dec) {
    __shared__ int s_y[NBG], s_x[NBG], s_d[NBG], s_b[NBG];
    int tid = threadIdx.x;
    int g = gb >> 7;
    int r = gb & 127;

    if (tid < NBG) {
        int box = g * NBG + tid;
        s_y[tid] = __ldg(&box_yx[box * 2]);
        s_x[tid] = __ldg(&box_yx[box * 2 + 1]);
        s_d[tid] = (__ldg(&dec[box * 3]) > 0 ? 1 : 0) |
                   (__ldg(&dec[box * 3 + 1]) > 0 ? 2 : 0) |
                   (__ldg(&dec[box * 3 + 2]) > 0 ? 4 : 0);
        s_b[tid] = box >> 4;
    }
    __syncthreads();

    int j = tid / 3;
    int c = tid - 3 * j;

    float acc_nr = 0.f;
    float acc_rt = 0.f;
#pragma unroll 8
    for (int k = 0; k < NBG; ++k) {
        int d = s_d[k];
        size_t base = (size_t)s_b[k] * (HW * HW * 3);
        if (d & 1) {
            int row = s_y[k] + ((d & 4) ? r : (PB - 1 - r));
            int col = s_x[k] + ((d & 2) ? (PB - 1 - j) : j);
            acc_rt += __ldg(&grads[base + ((size_t)row * HW + col) * 3 + c]);
        } else {
            int row = s_y[k] + ((d & 4) ? (PB - 1 - r) : r);
            int col = s_x[k] + ((d & 2) ? (PB - 1 - j) : j);
            acc_nr += __ldg(&grads[base + ((size_t)row * HW + col) * 3 + c]);
        }
    }
    g_nr[g][r][tid] = acc_nr;
    g_rt[g][r][tid] = acc_rt;

    __syncthreads();
    __threadfence();
    if (tid == 0) atomicAdd(&g_sync[1], 1);
}

// ---------------------------------------------------------------------------
// Role: paste. 4 blocks per box, 32 rows each. Pure stores of the transformed
// tile; later-box-wins via a compacted overlap list (usually empty).
// ---------------------------------------------------------------------------
__device__ void role_paste(int pb_, const int* __restrict__ box_yx,
                           const int* __restrict__ dec,
                           float* __restrict__ out) {
    int box = pb_ >> 2;
    int rbase = (pb_ & 3) * 32;
    int b = box >> 4;
    int n = box & 15;
    int tid = threadIdx.x;

    __shared__ int s_y0, s_x0, s_d;
    __shared__ int l_y[NPER], l_x[NPER];
    __shared__ int l_cnt;

    if (tid == 0) {
        s_y0 = __ldg(&box_yx[box * 2]);
        s_x0 = __ldg(&box_yx[box * 2 + 1]);
        s_d = (__ldg(&dec[box * 3]) > 0 ? 1 : 0) |
              (__ldg(&dec[box * 3 + 1]) > 0 ? 2 : 0) |
              (__ldg(&dec[box * 3 + 2]) > 0 ? 4 : 0);
        l_cnt = 0;
    }
    __syncthreads();

    if (tid >= n + 1 && tid < NPER) {
        int mb = b * NPER + tid;
        int ym = __ldg(&box_yx[mb * 2]);
        int xm = __ldg(&box_yx[mb * 2 + 1]);
        int ylo = s_y0 + rbase, yhi = s_y0 + rbase + 32;
        bool ovl = (ym < yhi) && (ym + PB > ylo) &&
                   (xm < s_x0 + PB) && (xm + PB > s_x0);
        if (ovl) {
            int idx = atomicAdd(&l_cnt, 1);
            l_y[idx] = ym;
            l_x[idx] = xm;
        }
    }

    if (tid == 0) {
        volatile int* p = &g_sync[0];
        while (*p < DS_BLOCKS) __nanosleep(64);
    }
    __syncthreads();

    int rx = tid / 3;
    int c = tid - 3 * rx;
    int d = s_d;
    int x1 = (d & 2) ? (PB - 1 - rx) : rx;
    int xg = s_x0 + rx;
    int cnt = l_cnt;

    for (int r = 0; r < 32; r++) {
        int ry = rbase + r;
        int yg = s_y0 + ry;
        bool skip = false;
        for (int m = 0; m < cnt; m++) {
            if ((unsigned)(yg - l_y[m]) < (unsigned)PB &&
                (unsigned)(xg - l_x[m]) < (unsigned)PB) { skip = true; break; }
        }
        if (skip) continue;
        int y2 = (d & 4) ? (PB - 1 - ry) : ry;
        float val;
        if (d & 1) {
            int sx_ = PB - 1 - y2;
            val = g_smallT[(sx_ * PB + x1) * 3 + c];
        } else {
            val = g_small[(y2 * PB + x1) * 3 + c];
        }
        out[((size_t)(b * HW + yg) * HW + xg) * 3 + c] = val;
    }
}

// ---------------------------------------------------------------------------
// Role: streaming copy, 8 rows/block, chunk-of-4 live state (no spills),
// coverage-masked stores, streaming hints kept (protect L2 reuse). Never waits.
// ---------------------------------------------------------------------------
__device__ void role_copy(int cb, const float* __restrict__ images,
                          const int* __restrict__ box_yx,
                          float* __restrict__ out) {
    int b = cb >> 7;                     // 128 blocks per image
    int ybase = (cb & 127) * ROWS_PER_CP;
    int tid = threadIdx.x;

    __shared__ unsigned s_cov[ROWS_PER_CP][32];   // 8 rows x 1024 bits

    if (tid < ROWS_PER_CP * 32) ((unsigned*)s_cov)[tid] = 0u;   // 256 < 384: safe
    __syncthreads();

    // build coverage: 128 threads = (box, row)
    if (tid < NPER * ROWS_PER_CP) {
        int bx_ = tid >> 3;              // box 0..15
        int r = tid & 7;                 // row 0..7
        int boxid = b * NPER + bx_;
        int y0 = __ldg(&box_yx[boxid * 2]);
        if ((unsigned)(ybase + r - y0) < (unsigned)PB) {
            int x0 = __ldg(&box_yx[boxid * 2 + 1]);
            int w0 = x0 >> 5, off = x0 & 31;
            if (off == 0) {
#pragma unroll
                for (int w = 0; w < 4; w++) atomicOr(&s_cov[r][w0 + w], 0xFFFFFFFFu);
            } else {
                atomicOr(&s_cov[r][w0], 0xFFFFFFFFu << off);
#pragma unroll
                for (int w = 1; w < 4; w++) atomicOr(&s_cov[r][w0 + w], 0xFFFFFFFFu);
                atomicOr(&s_cov[r][w0 + 4], 0xFFFFFFFFu >> (32 - off));
            }
        }
    }
    __syncthreads();

    size_t base4 = ((size_t)(b * HW + ybase)) * (HW * 3 / 4);
    const float4* src4 = (const float4*)images + base4;
    float4* dst4 = (float4*)out + base4;

    // 8 rows x 768 float4; process 2 rows (4 float4/thread) per h-iteration.
#pragma unroll
    for (int h = 0; h < 4; h++) {
        float4 v[4];
        int cc[4];
#pragma unroll
        for (int k = 0; k < 4; k++) {
            int row = h * 2 + (k >> 1);
            int qq = (k & 1) * THREADS + tid;         // float4 idx in row
            int pa = (qq * 4) / 3;                    // first pixel spanned
            int ca = (s_cov[row][pa >> 5] >> (pa & 31)) & 1;
            int cbit = (s_cov[row][(pa + 1) >> 5] >> ((pa + 1) & 31)) & 1;
            cc[k] = ca | (cbit << 1);
            if (cc[k] != 3)
                v[k] = __ldcs(&src4[row * 768 + qq]);
        }
#pragma unroll
        for (int k = 0; k < 4; k++) {
            if (cc[k] == 3) continue;                 // fully pasted
            int row = h * 2 + (k >> 1);
            int qq = (k & 1) * THREADS + tid;
            float4* dp = &dst4[row * 768 + qq];
            if (cc[k] == 0) {
                __stcs(dp, v[k]);
            } else {
                int fo = qq * 4;
                int pa = fo / 3;
                float* df = (float*)dp;
                const float* vf = (const float*)&v[k];
#pragma unroll
                for (int e = 0; e < 4; e++) {
                    int px = (fo + e) / 3;
                    int covered = (px == pa) ? (cc[k] & 1) : ((cc[k] >> 1) & 1);
                    if (!covered) df[e] = vf[e];
                }
            }
        }
    }
}

// ---------------------------------------------------------------------------
// Role: reduce gather partials + bilinear upsample 128->256 + analytic TV grad.
// ---------------------------------------------------------------------------
__device__ __forceinline__ float acc_at(int y, int x, int c) {
    float s = 0.f;
#pragma unroll
    for (int g = 0; g < NGRP; g++) {
        s += g_nr[g][y][x * 3 + c];
        s += g_rt[g][x][y * 3 + c];
    }
    return s;
}

__device__ void role_final(int fb, const float* __restrict__ patch,
                           float* __restrict__ agg) {
    if (threadIdx.x == 0) {
        volatile int* p = &g_sync[1];
        while (*p < GT_BLOCKS) __nanosleep(64);
    }
    __syncthreads();

    int t = fb * THREADS + threadIdx.x;
    int c = t % 3;
    int j = (t / 3) % PHW;
    int i = t / (PHW * 3);

    int ky = i >> 1, y0, y1; float wy0, wy1;
    if (i & 1) { y0 = ky;             y1 = min(ky + 1, PB - 1); wy0 = 0.75f; wy1 = 0.25f; }
    else       { y0 = max(ky - 1, 0); y1 = ky;                  wy0 = 0.25f; wy1 = 0.75f; }
    int kx = j >> 1, x0, x1; float wx0, wx1;
    if (j & 1) { x0 = kx;             x1 = min(kx + 1, PB - 1); wx0 = 0.75f; wx1 = 0.25f; }
    else       { x0 = max(kx - 1, 0); x1 = kx;                  wx0 = 0.25f; wx1 = 0.75f; }

    float v = wy0 * (wx0 * acc_at(y0, x0, c) + wx1 * acc_at(y0, x1, c))
            + wy1 * (wx0 * acc_at(y1, x0, c) + wx1 * acc_at(y1, x1, c));

    float pij = __ldg(&patch[(i * PHW + j) * 3 + c]);
    float a = (j < PHW - 1) ? (pij - __ldg(&patch[(i * PHW + j + 1) * 3 + c])) : 0.f;
    float bb = (i < PHW - 1) ? (pij - __ldg(&patch[((i + 1) * PHW + j) * 3 + c])) : 0.f;
    float g = (a + bb) * rsqrtf(a * a + bb * bb + 1e-12f);
    if (j > 0) {
        float pl = __ldg(&patch[(i * PHW + j - 1) * 3 + c]);
        float al = pl - pij;
        float bl = (i < PHW - 1) ? (pl - __ldg(&patch[((i + 1) * PHW + j - 1) * 3 + c])) : 0.f;
        g -= al * rsqrtf(al * al + bl * bl + 1e-12f);
    }
    if (i > 0) {
        float pu = __ldg(&patch[((i - 1) * PHW + j) * 3 + c]);
        float bu = pu - pij;
        float au = (j < PHW - 1) ? (pu - __ldg(&patch[((i - 1) * PHW + j + 1) * 3 + c])) : 0.f;
        g -= bu * rsqrtf(au * au + bu * bu + 1e-12f);
    }
    agg[t] = v + 0.5f * g;
}

// ---------------------------------------------------------------------------
// Mega kernel, R8/R16 layout: ds | gather | paste | copy | final.
// ---------------------------------------------------------------------------
__global__ void __launch_bounds__(THREADS, 4) k_mega(
        const float* __restrict__ images, const float* __restrict__ grads,
        const float* __restrict__ patch,
        const int* __restrict__ box_yx, const int* __restrict__ dec,
        float* __restrict__ out, float* __restrict__ agg) {
    int bid = blockIdx.x;
    if (bid < DS_BLOCKS) {
        role_downsample(bid, patch);
    } else if (bid < DS_BLOCKS + GT_BLOCKS) {
        role_gather(bid - DS_BLOCKS, grads, box_yx, dec);
    } else if (bid < DS_BLOCKS + GT_BLOCKS + PS_BLOCKS) {
        role_paste(bid - (DS_BLOCKS + GT_BLOCKS), box_yx, dec, out);
    } else if (bid < DS_BLOCKS + GT_BLOCKS + PS_BLOCKS + CP_BLOCKS) {
        role_copy(bid - (DS_BLOCKS + GT_BLOCKS + PS_BLOCKS), images, box_yx, out);
    } else {
        role_final(bid - (DS_BLOCKS + GT_BLOCKS + PS_BLOCKS + CP_BLOCKS), patch, agg);
    }
}

// ---------------------------------------------------------------------------
extern "C" void kernel_launch(void* const* d_in, const int* in_sizes, int n_in,
                              void* d_out, int out_size) {
    const float* images = (const float*)d_in[0];
    const float* grads  = (const float*)d_in[1];
    const float* patch  = (const float*)d_in[2];
    const int*   box_yx = (const int*)d_in[3];
    const int*   dec    = (const int*)d_in[4];

    float* out = (float*)d_out;
    size_t img_elems = (size_t)BIMG * HW * HW * 3;
    float* agg = out + img_elems;

    void* sptr = nullptr;
    cudaGetSymbolAddress(&sptr, g_sync);
    cudaMemsetAsync(sptr, 0, 2 * sizeof(int));

    k_mega<<<TOTAL_BLOCKS, THREADS>>>(images, grads, patch, box_yx, dec, out, agg);
}